// round 14
// baseline (speedup 1.0000x reference)
#include <cuda_runtime.h>
#include <cuda_fp16.h>
#include <cstdint>

// Problem dims
#define B_  64
#define S_  512
#define I_  512
#define H_  1024
#define G_  4096          // 4*H
#define BH_ (B_*H_)       // 65536
#define OUT_ELEMS (B_*S_*H_)   // 33554432

#define NCTA  128
#define NTHR  544         // 512 consumers + 32 producer warp
#define NCONS 512
#define NCH   16          // K-chunks of 64 per 1024-wide matrix (storage layout)

// persistent-kernel smem plan (all-fp16 staging)
// 5 stages x 32KB: [0,16384) B(h, fp16), [16384,24576) A0(fp16), [24576,32768) A1(fp16)
// partial-sum buffer (139264 B) overlays the 163840 B stage area after consumption
#define STG_SZ 32768
#define NSTG   5
#define SM_BI  163840
#define SM_MB  163968     // full[5] @ +0, empty[5] @ +40
#define SM_TOT 164096

// ---------------- device scratch (static, allowed) ----------------
__device__ float  g_Wx0p[G_*I_];            // tf32-rounded, gate-permuted rows (for precompute)
__device__ float  g_b0p[G_];                // bx0+bh0, permuted (folded into G0)
__device__ float  g_b1p[G_];                // bx1+bh1, permuted
__device__ uint2  g_A0h[(size_t)NCTA*NCH*512]; // Wh0 fragment-major fp16 pairs (8MB)
__device__ uint2  g_A1h[(size_t)NCTA*NCH*512]; // Wx1
__device__ uint2  g_A2h[(size_t)NCTA*NCH*512]; // Wh1
__device__ float  g_G0[(size_t)S_*B_*G_];   // x-path preactivations [t][b][prow] (512MB)
__device__ __half g_h0I[2][65536];          // h0 fragment-major fp16, double buffered
__device__ __half g_h1I[2][65536];          // h1 fragment-major fp16
__device__ unsigned g_barCount;
__device__ volatile unsigned g_barGen;

// ---------------- helpers ----------------
__device__ __forceinline__ float f2tf_f(float f) {
    uint32_t r;
    asm("cvt.rna.tf32.f32 %0, %1;" : "=r"(r) : "f"(f));
    return __uint_as_float(r);
}

__device__ __forceinline__ void mma_tf32(float* d, float4 a, float2 b) {
    asm volatile(
        "mma.sync.aligned.m16n8k8.row.col.f32.tf32.tf32.f32 "
        "{%0,%1,%2,%3}, {%4,%5,%6,%7}, {%8,%9}, {%0,%1,%2,%3};\n"
        : "+f"(d[0]), "+f"(d[1]), "+f"(d[2]), "+f"(d[3])
        : "r"(__float_as_uint(a.x)), "r"(__float_as_uint(a.y)),
          "r"(__float_as_uint(a.z)), "r"(__float_as_uint(a.w)),
          "r"(__float_as_uint(b.x)), "r"(__float_as_uint(b.y)));
}

__device__ __forceinline__ float4 frag_h2(uint2 ap) {
    float2 lo = __half22float2(*(__half2*)&ap.x);
    float2 hi = __half22float2(*(__half2*)&ap.y);
    return make_float4(lo.x, lo.y, hi.x, hi.y);
}

__device__ __forceinline__ float sigmoidf_(float x) { return 1.0f / (1.0f + expf(-x)); }

// ---- TMA bulk + mbarrier machinery ----
__device__ __forceinline__ void mbar_init(uint32_t addr, uint32_t count) {
    asm volatile("mbarrier.init.shared.b64 [%0], %1;" :: "r"(addr), "r"(count) : "memory");
}
__device__ __forceinline__ void mbar_expect_tx(uint32_t addr, uint32_t bytes) {
    asm volatile("mbarrier.arrive.expect_tx.shared.b64 _, [%0], %1;"
                 :: "r"(addr), "r"(bytes) : "memory");
}
__device__ __forceinline__ void mbar_arrive(uint32_t addr) {
    asm volatile("mbarrier.arrive.shared.b64 _, [%0];" :: "r"(addr) : "memory");
}
__device__ __forceinline__ void bulk_g2s(uint32_t dst, const void* src,
                                         uint32_t bytes, uint32_t mbar) {
    asm volatile(
        "cp.async.bulk.shared::cta.global.mbarrier::complete_tx::bytes [%0], [%1], %2, [%3];"
        :: "r"(dst), "l"(src), "r"(bytes), "r"(mbar) : "memory");
}
__device__ __forceinline__ void mbar_wait(uint32_t mbar, uint32_t parity) {
    asm volatile(
        "{\n\t"
        ".reg .pred P;\n\t"
        "WAIT_LOOP_%=:\n\t"
        "mbarrier.try_wait.parity.acquire.cta.shared::cta.b64 P, [%0], %1, 0x989680;\n\t"
        "@P bra.uni WAIT_DONE_%=;\n\t"
        "bra.uni WAIT_LOOP_%=;\n\t"
        "WAIT_DONE_%=:\n\t"
        "}"
        :: "r"(mbar), "r"(parity) : "memory");
}

// grid barrier (all NCTA CTAs co-resident) — proven atomic version
__device__ __forceinline__ void gsync() {
    __syncthreads();
    if (threadIdx.x == 0) {
        unsigned gen = g_barGen;
        __threadfence();
        if (atomicAdd(&g_barCount, 1u) == NCTA - 1) {
            g_barCount = 0;
            __threadfence();
            g_barGen = gen + 1;
        } else {
            while (g_barGen == gen) { }
            __threadfence();
        }
    }
    __syncthreads();
}

// Row permutation: prow = (u/8)*32 + q*8 + (u%8); CTA c owns units [8c,8c+8).

// ---------------- convert: natural Wx0 + biases ----------------
__global__ void __launch_bounds__(256) convert_nat(
    const float* __restrict__ Wx0, const float* __restrict__ bx0, const float* __restrict__ bh0,
    const float* __restrict__ bx1, const float* __restrict__ bh1)
{
    const int total = G_ * I_;
    for (int i = blockIdx.x * blockDim.x + threadIdx.x; i < total;
         i += gridDim.x * blockDim.x) {
        int prow = i / I_;
        int k    = i - prow * I_;
        int u    = ((prow >> 5) << 3) + (prow & 7);
        int q    = (prow >> 3) & 3;
        int orig = q * H_ + u;
        g_Wx0p[i] = f2tf_f(Wx0[(size_t)orig * I_ + k]);
        if (k == 0) {
            g_b0p[prow] = bx0[orig] + bh0[orig];
            g_b1p[prow] = bx1[orig] + bh1[orig];
        }
    }
}

// ---------------- convert: fragment-major recurrent weights (fp16 pairs) ----------------
__global__ void __launch_bounds__(256) convert_frag(
    const float* __restrict__ Wh0, const float* __restrict__ Wx1, const float* __restrict__ Wh1)
{
    const int total = NCTA * NCH * 512;
    for (int idx = blockIdx.x * blockDim.x + threadIdx.x; idx < total;
         idx += gridDim.x * blockDim.x) {
        int lane = idx & 31;
        int kk   = (idx >> 5) & 7;
        int wm   = (idx >> 8) & 1;
        int ch   = (idx >> 9) & 15;
        int c    = idx >> 13;
        int g4 = lane >> 2, t4 = lane & 3;
        int p0 = wm * 16 + g4;
        int q0 = p0 >> 3, v = p0 & 7;
        int o0 = q0 * H_ + c * 8 + v;
        int k  = ch * 64 + kk * 8 + t4;
        size_t r0 = (size_t)o0 * H_ + k;
        size_t r1 = r0 + (size_t)H_ * H_;
        uint2 w0, w1, w2;
        __half2 h;
        h = __floats2half2_rn(Wh0[r0], Wh0[r1]);         w0.x = *(uint32_t*)&h;
        h = __floats2half2_rn(Wh0[r0 + 4], Wh0[r1 + 4]); w0.y = *(uint32_t*)&h;
        h = __floats2half2_rn(Wx1[r0], Wx1[r1]);         w1.x = *(uint32_t*)&h;
        h = __floats2half2_rn(Wx1[r0 + 4], Wx1[r1 + 4]); w1.y = *(uint32_t*)&h;
        h = __floats2half2_rn(Wh1[r0], Wh1[r1]);         w2.x = *(uint32_t*)&h;
        h = __floats2half2_rn(Wh1[r0 + 4], Wh1[r1 + 4]); w2.y = *(uint32_t*)&h;
        g_A0h[idx] = w0;
        g_A1h[idx] = w1;
        g_A2h[idx] = w2;
    }
}

// ---------------- init (every replay): barrier state only ----------------
__global__ void init_kernel() {
    if (threadIdx.x == 0) { g_barCount = 0; g_barGen = 0; }
}

// ---------------- x-path precompute: G0 = x@Wx0p^T + b0p ----------------
__global__ void __launch_bounds__(256, 1) precompute_kernel(const float* __restrict__ x)
{
    __shared__ float As[128][20];
    __shared__ float Bs[128][20];

    const int tid  = threadIdx.x;
    const int w    = tid >> 5;
    const int lane = tid & 31;
    const int wM   = w >> 2;
    const int wN   = w & 3;
    const int mBase = blockIdx.y * 128;
    const int nBase = blockIdx.x * 128;
    const int g4 = lane >> 2;
    const int t4 = lane & 3;

    float acc[4][4][4];
#pragma unroll
    for (int mt = 0; mt < 4; mt++)
#pragma unroll
        for (int nt = 0; nt < 4; nt++)
#pragma unroll
            for (int e = 0; e < 4; e++) acc[mt][nt][e] = 0.0f;

    for (int kc = 0; kc < I_; kc += 16) {
#pragma unroll
        for (int it = 0; it < 2; it++) {
            int i  = tid + it * 256;
            int r  = i >> 2;
            int c4 = (i & 3) * 4;
            int m  = mBase + r;
            int tt = m >> 6;
            int bb = m & 63;
            float4 v = *(const float4*)(x + ((size_t)bb * S_ + tt) * I_ + kc + c4);
            As[r][c4 + 0] = f2tf_f(v.x); As[r][c4 + 1] = f2tf_f(v.y);
            As[r][c4 + 2] = f2tf_f(v.z); As[r][c4 + 3] = f2tf_f(v.w);
        }
#pragma unroll
        for (int it = 0; it < 2; it++) {
            int i  = tid + it * 256;
            int r  = i >> 2;
            int c4 = (i & 3) * 4;
            float4 v = *(const float4*)(g_Wx0p + (size_t)(nBase + r) * I_ + kc + c4);
            Bs[r][c4 + 0] = v.x; Bs[r][c4 + 1] = v.y;
            Bs[r][c4 + 2] = v.z; Bs[r][c4 + 3] = v.w;
        }
        __syncthreads();

#pragma unroll
        for (int kk = 0; kk < 2; kk++) {
            int k = kk * 8;
            float2 bf[4];
#pragma unroll
            for (int nt = 0; nt < 4; nt++) {
                int n = wN * 32 + nt * 8 + g4;
                bf[nt] = make_float2(Bs[n][k + t4], Bs[n][k + t4 + 4]);
            }
#pragma unroll
            for (int mt = 0; mt < 4; mt++) {
                int r = wM * 64 + mt * 16 + g4;
                float4 af = make_float4(As[r][k + t4], As[r + 8][k + t4],
                                        As[r][k + t4 + 4], As[r + 8][k + t4 + 4]);
#pragma unroll
                for (int nt = 0; nt < 4; nt++)
                    mma_tf32(acc[mt][nt], af, bf[nt]);
            }
        }
        __syncthreads();
    }

#pragma unroll
    for (int mt = 0; mt < 4; mt++) {
        int r0 = mBase + wM * 64 + mt * 16 + g4;
        int r1 = r0 + 8;
#pragma unroll
        for (int nt = 0; nt < 4; nt++) {
            int n0 = nBase + wN * 32 + nt * 8 + t4 * 2;
            float2 bv = *(const float2*)(g_b0p + n0);
            *(float2*)(g_G0 + (size_t)r0 * G_ + n0) =
                make_float2(acc[mt][nt][0] + bv.x, acc[mt][nt][1] + bv.y);
            *(float2*)(g_G0 + (size_t)r1 * G_ + n0) =
                make_float2(acc[mt][nt][2] + bv.x, acc[mt][nt][3] + bv.y);
        }
    }
}

// ---------------- persistent recurrent kernel (all-fp16 staging, 5-stage ring) ----
// Consumer warps 0..15: ks = w&7 (K-eighth), wm = w>>3 (prow half), full N=64.
// Producer warp 16 (tid 512): issues TMA for 16 K=128 chunks/step into 5 stages.
// Chunks 0..7: {B=h0, A0=Wh0, A1=Wx1}; chunks 8..15: {B=h1, A0slot=Wh1}. All fp16.
// Stage s = ch%5, n = ch/5; uses/step u_s = {4,3,3,3,3}:
//   full  parity = ((s?t:0)+n)&1 ;  empty parity = ((s?t:0)+n+1)&1 (skip t==0,n==0)

__global__ void __launch_bounds__(NTHR, 1) lstm_persist(float* __restrict__ out)
{
    extern __shared__ char sm[];
    float* sB = (float*)(sm + SM_BI);
    float* P  = (float*)sm;                       // partial buffer (overlay)
    const uint32_t smBase = (uint32_t)__cvta_generic_to_shared(sm);
    const uint32_t fullB  = smBase + SM_MB;
    const uint32_t emptyB = smBase + SM_MB + 40;

    const int c    = blockIdx.x;
    const int tid  = threadIdx.x;
    const int w    = tid >> 5;
    const int lane = tid & 31;
    const int ks   = w & 7;          // consumer K-eighth
    const int wm   = (w >> 3) & 1;   // prow half
    const int g4   = lane >> 2;
    const int t4   = lane & 3;
    const int v    = tid & 7;        // unit within CTA (consumers)
    const int b    = tid >> 3;       // batch (consumers, <64)
    const int u    = c * 8 + v;
    const int fidx = ((c * 256 + ((b >> 3) * 4 + (v & 3)) * 8 + (b & 7)) << 1) + (v >> 2);

    if (tid == 0) {
#pragma unroll
        for (int s = 0; s < NSTG; s++) {
            mbar_init(fullB  + s * 8, 1);
            mbar_init(emptyB + s * 8, 16);
        }
    }
    if (tid < 32) sB[tid] = g_b1p[c * 32 + tid];
    asm volatile("fence.proxy.async.shared::cta;" ::: "memory");
    __syncthreads();

    float c0r = 0.f, c1r = 0.f;

    // preamble: h0[0] from G0[0] (h=0), zero h1[-1] fragments
    if (tid < NCONS) {
        __half* h0w0 = g_h0I[0];
        __half* h1w0 = g_h1I[0];
        size_t gbase = (size_t)b * G_ + c * 32;
        float gi = g_G0[gbase + v];
        float go = g_G0[gbase + 16 + v];
        float gg = g_G0[gbase + 24 + v];
        float cn = sigmoidf_(gi) * tanhf(gg);
        float hn = sigmoidf_(go) * tanhf(cn);
        c0r = cn;
        h0w0[fidx] = __float2half(hn);
        h1w0[fidx] = __float2half(0.f);
    }
    gsync();

    const uint2* a0B = g_A0h + (size_t)c * (NCH * 512);
    const uint2* a1B = g_A1h + (size_t)c * (NCH * 512);
    const uint2* a2B = g_A2h + (size_t)c * (NCH * 512);

    for (int t = 0; t < S_; t++) {
        const __half* bH0 = g_h0I[t & 1];          // h0[t]
        __half*       wH0 = g_h0I[(t + 1) & 1];
        const __half* bH1 = g_h1I[t & 1];          // h1[t-1]
        __half*       wH1 = g_h1I[(t + 1) & 1];

        // consumers: prefetch next layer0's G0 operands
        float p_gi = 0.f, p_gf = 0.f, p_go = 0.f, p_gg = 0.f;
        if (tid < NCONS && t + 1 < S_) {
            size_t gb = ((size_t)(t + 1) * B_ + b) * G_ + c * 32;
            p_gi = g_G0[gb + v];
            p_gf = g_G0[gb + 8 + v];
            p_go = g_G0[gb + 16 + v];
            p_gg = g_G0[gb + 24 + v];
        }

        float acc0[8][4], acc1[8][4];
#pragma unroll
        for (int bt = 0; bt < 8; bt++)
#pragma unroll
            for (int e = 0; e < 4; e++) { acc0[bt][e] = 0.f; acc1[bt][e] = 0.f; }

        if (tid == NCONS) {
            // ---------------- producer ----------------
            for (int ch = 0; ch < 16; ch++) {
                int s = ch % 5, n = ch / 5;
                if (t > 0 || n > 0) {
                    uint32_t par = (uint32_t)((((s != 0) ? (t & 1) : 0) + n + 1) & 1);
                    mbar_wait(emptyB + s * 8, par);
                }
                uint32_t sb = smBase + (uint32_t)s * STG_SZ;
                uint32_t fb = fullB + s * 8;
                if (ch < 8) {
                    mbar_expect_tx(fb, 32768u);
                    bulk_g2s(sb,          bH0 + (size_t)ch * 8192, 16384, fb);
                    bulk_g2s(sb + 16384,  a0B + (size_t)ch * 1024, 8192,  fb);
                    bulk_g2s(sb + 24576,  a1B + (size_t)ch * 1024, 8192,  fb);
                } else {
                    int cc = ch - 8;
                    mbar_expect_tx(fb, 24576u);
                    bulk_g2s(sb,          bH1 + (size_t)cc * 8192, 16384, fb);
                    bulk_g2s(sb + 16384,  a2B + (size_t)cc * 1024, 8192,  fb);
                }
            }
        } else if (tid < NCONS) {
            // ---------------- consumers ----------------
            // chunks 0..7 : Wh0 -> acc0, Wx1 -> acc1  (B = h0[t], all fp16)
            for (int ch = 0; ch < 8; ch++) {
                int s = ch % 5, n = ch / 5;
                uint32_t par = (uint32_t)((((s != 0) ? (t & 1) : 0) + n) & 1);
                mbar_wait(fullB + s * 8, par);
                const char* st = sm + s * STG_SZ;
                const uint2* A0f = (const uint2*)(st + 16384);
                const uint2* A1f = (const uint2*)(st + 24576);
#pragma unroll
                for (int half = 0; half < 2; half++) {
                    int aidx = half * 512 + (wm * 8 + ks) * 32 + lane;
                    float4 a0 = frag_h2(A0f[aidx]);
                    float4 a1 = frag_h2(A1f[aidx]);
                    const char* bb = st + (ks + half * 8) * 1024 + t4 * 32 + g4 * 4;
#pragma unroll
                    for (int bt = 0; bt < 8; bt++) {
                        __half2 hh = *(const __half2*)(bb + bt * 128);
                        float2 bf = __half22float2(hh);
                        mma_tf32(acc0[bt], a0, bf);
                        mma_tf32(acc1[bt], a1, bf);
                    }
                }
                if (lane == 0) mbar_arrive(emptyB + s * 8);
            }
            // chunks 8..15 : Wh1 -> acc1  (B = h1[t-1], all fp16)
            for (int ch = 8; ch < 16; ch++) {
                int s = ch % 5, n = ch / 5;
                uint32_t par = (uint32_t)((((s != 0) ? (t & 1) : 0) + n) & 1);
                mbar_wait(fullB + s * 8, par);
                const char* st = sm + s * STG_SZ;
                const uint2* A0f = (const uint2*)(st + 16384);
#pragma unroll
                for (int half = 0; half < 2; half++) {
                    int aidx = half * 512 + (wm * 8 + ks) * 32 + lane;
                    float4 a0 = frag_h2(A0f[aidx]);
                    const char* bb = st + (ks + half * 8) * 1024 + t4 * 32 + g4 * 4;
#pragma unroll
                    for (int bt = 0; bt < 8; bt++) {
                        __half2 hh = *(const __half2*)(bb + bt * 128);
                        float2 bf = __half22float2(hh);
                        mma_tf32(acc1[bt], a0, bf);
                    }
                }
                if (lane == 0) mbar_arrive(emptyB + s * 8);
            }
        }
        __syncthreads();   // all stages consumed; safe to overlay partials

        // ---- write K-split partials (row stride 68 floats, 4352 floats per ks) ----
        if (tid < NCONS) {
            int r0 = wm * 16 + g4;
            int base0 = ks * 4352;
#pragma unroll
            for (int bt = 0; bt < 8; bt++) {
                int col = bt * 8 + t4 * 2;
                *(float2*)&P[base0 + r0 * 68 + col]        = make_float2(acc0[bt][0], acc0[bt][1]);
                *(float2*)&P[base0 + (r0 + 8) * 68 + col]  = make_float2(acc0[bt][2], acc0[bt][3]);
                *(float2*)&P[base0 + 2176 + r0 * 68 + col]       = make_float2(acc1[bt][0], acc1[bt][1]);
                *(float2*)&P[base0 + 2176 + (r0 + 8) * 68 + col] = make_float2(acc1[bt][2], acc1[bt][3]);
            }
        }
        __syncthreads();

        // ---- reduce 8 partials + cell epilogues ----
        if (tid < NCONS) {
            float g0[4], g1[4];
#pragma unroll
            for (int q = 0; q < 4; q++) {
                int row = q * 8 + v;
                float s0 = 0.f, s1 = 0.f;
#pragma unroll
                for (int kr = 0; kr < 8; kr++) {
                    s0 += P[kr * 4352 + row * 68 + b];
                    s1 += P[kr * 4352 + 2176 + row * 68 + b];
                }
                g0[q] = s0; g1[q] = s1;
            }
            // layer 1 step t
            {
                float gi = g1[0] + sB[v];
                float gf = g1[1] + sB[8 + v];
                float go = g1[2] + sB[16 + v];
                float gg = g1[3] + sB[24 + v];
                float cn = sigmoidf_(gf) * c1r + sigmoidf_(gi) * tanhf(gg);
                float hn = sigmoidf_(go) * tanhf(cn);
                c1r = cn;
                out[((size_t)b * S_ + t) * H_ + u] = hn;
                wH1[fidx] = __float2half(hn);
                if (t == S_ - 1) {
                    out[(size_t)OUT_ELEMS + 1ull * BH_ + (size_t)b * H_ + u] = hn;
                    out[(size_t)OUT_ELEMS + 3ull * BH_ + (size_t)b * H_ + u] = cn;
                }
            }
            // layer 0 step t+1
            if (t < S_ - 1) {
                float gi = g0[0] + p_gi;
                float gf = g0[1] + p_gf;
                float go = g0[2] + p_go;
                float gg = g0[3] + p_gg;
                float cn = sigmoidf_(gf) * c0r + sigmoidf_(gi) * tanhf(gg);
                float hn = sigmoidf_(go) * tanhf(cn);
                c0r = cn;
                wH0[fidx] = __float2half(hn);
                if (t == S_ - 2) {
                    out[(size_t)OUT_ELEMS + (size_t)b * H_ + u]              = hn;
                    out[(size_t)OUT_ELEMS + 2ull * BH_ + (size_t)b * H_ + u] = cn;
                }
            }
        }
        if (t + 1 < S_) gsync();
    }
}

// ---------------- launch ----------------
extern "C" void kernel_launch(void* const* d_in, const int* in_sizes, int n_in,
                              void* d_out, int out_size)
{
    const float* x   = (const float*)d_in[0];
    const float* Wx0 = (const float*)d_in[1];
    const float* Wh0 = (const float*)d_in[2];
    const float* bx0 = (const float*)d_in[3];
    const float* bh0 = (const float*)d_in[4];
    const float* Wx1 = (const float*)d_in[5];
    const float* Wh1 = (const float*)d_in[6];
    const float* bx1 = (const float*)d_in[7];
    const float* bh1 = (const float*)d_in[8];
    float* out = (float*)d_out;

    static bool attr_done = false;
    if (!attr_done) {
        cudaFuncSetAttribute(lstm_persist,
                             cudaFuncAttributeMaxDynamicSharedMemorySize, SM_TOT);
        attr_done = true;
    }

    convert_nat<<<2048, 256>>>(Wx0, bx0, bh0, bx1, bh1);
    convert_frag<<<4096, 256>>>(Wh0, Wx1, Wh1);
    init_kernel<<<1, 32>>>();
    precompute_kernel<<<dim3(G_ / 128, (S_ * B_) / 128), 256>>>(x);
    lstm_persist<<<NCTA, NTHR, SM_TOT>>>(out);
}

// round 15
// speedup vs baseline: 1.2962x; 1.2962x over previous
#include <cuda_runtime.h>
#include <cuda_fp16.h>
#include <cstdint>

// Problem dims
#define B_  64
#define S_  512
#define I_  512
#define H_  1024
#define G_  4096          // 4*H
#define BH_ (B_*H_)       // 65536
#define OUT_ELEMS (B_*S_*H_)   // 33554432

#define NCTA  128
#define NTHR  544         // 512 consumers + 32 producer warp
#define NCONS 512

// persistent-kernel smem plan (all-fp16 staging, fp16 mma fragments)
// 5 stages x 32KB: [0,16384) B(h img), [16384,24576) A0 frags, [24576,32768) A1 frags
// partial-sum buffer (139264 B) overlays the 163840 B stage area after consumption
#define STG_SZ 32768
#define NSTG   5
#define SM_BI  163840
#define SM_MB  163968     // full[5] @ +0, empty[5] @ +40
#define SM_TOT 164096

// ---------------- device scratch (static, allowed) ----------------
__device__ float  g_Wx0p[G_*I_];            // tf32-rounded, gate-permuted rows (for precompute)
__device__ float  g_b0p[G_];                // bx0+bh0, permuted (folded into G0)
__device__ float  g_b1p[G_];                // bx1+bh1, permuted
// fp16 k16-fragment weights: [c][ch(8)][frag(512)] uint4 (8MB each)
__device__ uint4  g_A0f[(size_t)NCTA*8*512];   // Wh0
__device__ uint4  g_A1f[(size_t)NCTA*8*512];   // Wx1
__device__ uint4  g_A2f[(size_t)NCTA*8*512];   // Wh1
__device__ float  g_G0[(size_t)S_*B_*G_];   // x-path preactivations [t][b][prow] (512MB)
__device__ __half g_h0I[2][65536];          // h0 B-fragment image fp16, double buffered
__device__ __half g_h1I[2][65536];          // h1 image
__device__ unsigned g_barCount;
__device__ volatile unsigned g_barGen;

// ---------------- helpers ----------------
__device__ __forceinline__ float f2tf_f(float f) {
    uint32_t r;
    asm("cvt.rna.tf32.f32 %0, %1;" : "=r"(r) : "f"(f));
    return __uint_as_float(r);
}

// legacy tf32 mma (precompute kernel only)
__device__ __forceinline__ void mma_tf32(float* d, float4 a, float2 b) {
    asm volatile(
        "mma.sync.aligned.m16n8k8.row.col.f32.tf32.tf32.f32 "
        "{%0,%1,%2,%3}, {%4,%5,%6,%7}, {%8,%9}, {%0,%1,%2,%3};\n"
        : "+f"(d[0]), "+f"(d[1]), "+f"(d[2]), "+f"(d[3])
        : "r"(__float_as_uint(a.x)), "r"(__float_as_uint(a.y)),
          "r"(__float_as_uint(a.z)), "r"(__float_as_uint(a.w)),
          "r"(__float_as_uint(b.x)), "r"(__float_as_uint(b.y)));
}

// fp16 m16n8k16 mma, fp32 accumulate
__device__ __forceinline__ void mma_f16(float* d, uint4 a, uint2 b) {
    asm volatile(
        "mma.sync.aligned.m16n8k16.row.col.f32.f16.f16.f32 "
        "{%0,%1,%2,%3}, {%4,%5,%6,%7}, {%8,%9}, {%0,%1,%2,%3};\n"
        : "+f"(d[0]), "+f"(d[1]), "+f"(d[2]), "+f"(d[3])
        : "r"(a.x), "r"(a.y), "r"(a.z), "r"(a.w), "r"(b.x), "r"(b.y));
}

__device__ __forceinline__ float sigmoidf_(float x) { return 1.0f / (1.0f + expf(-x)); }

// ---- TMA bulk + mbarrier machinery ----
__device__ __forceinline__ void mbar_init(uint32_t addr, uint32_t count) {
    asm volatile("mbarrier.init.shared.b64 [%0], %1;" :: "r"(addr), "r"(count) : "memory");
}
__device__ __forceinline__ void mbar_expect_tx(uint32_t addr, uint32_t bytes) {
    asm volatile("mbarrier.arrive.expect_tx.shared.b64 _, [%0], %1;"
                 :: "r"(addr), "r"(bytes) : "memory");
}
__device__ __forceinline__ void mbar_arrive(uint32_t addr) {
    asm volatile("mbarrier.arrive.shared.b64 _, [%0];" :: "r"(addr) : "memory");
}
__device__ __forceinline__ void bulk_g2s(uint32_t dst, const void* src,
                                         uint32_t bytes, uint32_t mbar) {
    asm volatile(
        "cp.async.bulk.shared::cta.global.mbarrier::complete_tx::bytes [%0], [%1], %2, [%3];"
        :: "r"(dst), "l"(src), "r"(bytes), "r"(mbar) : "memory");
}
__device__ __forceinline__ void mbar_wait(uint32_t mbar, uint32_t parity) {
    asm volatile(
        "{\n\t"
        ".reg .pred P;\n\t"
        "WAIT_LOOP_%=:\n\t"
        "mbarrier.try_wait.parity.acquire.cta.shared::cta.b64 P, [%0], %1, 0x989680;\n\t"
        "@P bra.uni WAIT_DONE_%=;\n\t"
        "bra.uni WAIT_LOOP_%=;\n\t"
        "WAIT_DONE_%=:\n\t"
        "}"
        :: "r"(mbar), "r"(parity) : "memory");
}

// grid barrier (all NCTA CTAs co-resident) — proven atomic version
__device__ __forceinline__ void gsync() {
    __syncthreads();
    if (threadIdx.x == 0) {
        unsigned gen = g_barGen;
        __threadfence();
        if (atomicAdd(&g_barCount, 1u) == NCTA - 1) {
            g_barCount = 0;
            __threadfence();
            g_barGen = gen + 1;
        } else {
            while (g_barGen == gen) { }
            __threadfence();
        }
    }
    __syncthreads();
}

// Row permutation: local row p (0..31) of CTA c: gate q = p>>3, unit v = p&7,
// original row = q*H + c*8 + v. prow(global) = c*32 + p.

// ---------------- convert: natural Wx0 + biases ----------------
__global__ void __launch_bounds__(256) convert_nat(
    const float* __restrict__ Wx0, const float* __restrict__ bx0, const float* __restrict__ bh0,
    const float* __restrict__ bx1, const float* __restrict__ bh1)
{
    const int total = G_ * I_;
    for (int i = blockIdx.x * blockDim.x + threadIdx.x; i < total;
         i += gridDim.x * blockDim.x) {
        int prow = i / I_;
        int k    = i - prow * I_;
        int u    = ((prow >> 5) << 3) + (prow & 7);
        int q    = (prow >> 3) & 3;
        int orig = q * H_ + u;
        g_Wx0p[i] = f2tf_f(Wx0[(size_t)orig * I_ + k]);
        if (k == 0) {
            g_b0p[prow] = bx0[orig] + bh0[orig];
            g_b1p[prow] = bx1[orig] + bh1[orig];
        }
    }
}

// ---------------- convert: k16-fragment fp16 recurrent weights ----------------
// frag layout per chunk (K=128): f = (wm*8+ks)*32 + lane -> uint4 {a0,a1,a2,a3}
//   p0 = wm*16 + (lane>>2); p1 = p0+8; k = ks*16 + (lane&3)*2
//   a0={W[p0][k],W[p0][k+1]} a1={W[p1][k],...} a2={W[p0][k+8],...} a3={W[p1][k+8],...}
__global__ void __launch_bounds__(256) convert_frag(
    const float* __restrict__ Wh0, const float* __restrict__ Wx1, const float* __restrict__ Wh1)
{
    const int total = NCTA * 8 * 512;
    for (int idx = blockIdx.x * blockDim.x + threadIdx.x; idx < total;
         idx += gridDim.x * blockDim.x) {
        int lane = idx & 31;
        int ks   = (idx >> 5) & 7;
        int wm   = (idx >> 8) & 1;
        int ch   = (idx >> 9) & 7;
        int c    = idx >> 12;
        int p0 = wm * 16 + (lane >> 2);
        int p1 = p0 + 8;
        int q0 = p0 >> 3, v0 = p0 & 7;
        int q1 = p1 >> 3, v1 = p1 & 7;
        size_t o0 = (size_t)(q0 * H_ + c * 8 + v0) * H_;
        size_t o1 = (size_t)(q1 * H_ + c * 8 + v1) * H_;
        int k  = ch * 128 + ks * 16 + (lane & 3) * 2;
        uint4 w; __half2 h;
        #define PACK(W, dst) \
            h = __floats2half2_rn(W[o0 + k],     W[o0 + k + 1]); dst.x = *(uint32_t*)&h; \
            h = __floats2half2_rn(W[o1 + k],     W[o1 + k + 1]); dst.y = *(uint32_t*)&h; \
            h = __floats2half2_rn(W[o0 + k + 8], W[o0 + k + 9]); dst.z = *(uint32_t*)&h; \
            h = __floats2half2_rn(W[o1 + k + 8], W[o1 + k + 9]); dst.w = *(uint32_t*)&h;
        PACK(Wh0, w); g_A0f[idx] = w;
        PACK(Wx1, w); g_A1f[idx] = w;
        PACK(Wh1, w); g_A2f[idx] = w;
        #undef PACK
    }
}

// ---------------- init (every replay): barrier state only ----------------
__global__ void init_kernel() {
    if (threadIdx.x == 0) { g_barCount = 0; g_barGen = 0; }
}

// ---------------- x-path precompute: G0 = x@Wx0p^T + b0p ----------------
__global__ void __launch_bounds__(256, 1) precompute_kernel(const float* __restrict__ x)
{
    __shared__ float As[128][20];
    __shared__ float Bs[128][20];

    const int tid  = threadIdx.x;
    const int w    = tid >> 5;
    const int lane = tid & 31;
    const int wM   = w >> 2;
    const int wN   = w & 3;
    const int mBase = blockIdx.y * 128;
    const int nBase = blockIdx.x * 128;
    const int g4 = lane >> 2;
    const int t4 = lane & 3;

    float acc[4][4][4];
#pragma unroll
    for (int mt = 0; mt < 4; mt++)
#pragma unroll
        for (int nt = 0; nt < 4; nt++)
#pragma unroll
            for (int e = 0; e < 4; e++) acc[mt][nt][e] = 0.0f;

    for (int kc = 0; kc < I_; kc += 16) {
#pragma unroll
        for (int it = 0; it < 2; it++) {
            int i  = tid + it * 256;
            int r  = i >> 2;
            int c4 = (i & 3) * 4;
            int m  = mBase + r;
            int tt = m >> 6;
            int bb = m & 63;
            float4 v = *(const float4*)(x + ((size_t)bb * S_ + tt) * I_ + kc + c4);
            As[r][c4 + 0] = f2tf_f(v.x); As[r][c4 + 1] = f2tf_f(v.y);
            As[r][c4 + 2] = f2tf_f(v.z); As[r][c4 + 3] = f2tf_f(v.w);
        }
#pragma unroll
        for (int it = 0; it < 2; it++) {
            int i  = tid + it * 256;
            int r  = i >> 2;
            int c4 = (i & 3) * 4;
            float4 v = *(const float4*)(g_Wx0p + (size_t)(nBase + r) * I_ + kc + c4);
            Bs[r][c4 + 0] = v.x; Bs[r][c4 + 1] = v.y;
            Bs[r][c4 + 2] = v.z; Bs[r][c4 + 3] = v.w;
        }
        __syncthreads();

#pragma unroll
        for (int kk = 0; kk < 2; kk++) {
            int k = kk * 8;
            float2 bf[4];
#pragma unroll
            for (int nt = 0; nt < 4; nt++) {
                int n = wN * 32 + nt * 8 + g4;
                bf[nt] = make_float2(Bs[n][k + t4], Bs[n][k + t4 + 4]);
            }
#pragma unroll
            for (int mt = 0; mt < 4; mt++) {
                int r = wM * 64 + mt * 16 + g4;
                float4 af = make_float4(As[r][k + t4], As[r + 8][k + t4],
                                        As[r][k + t4 + 4], As[r + 8][k + t4 + 4]);
#pragma unroll
                for (int nt = 0; nt < 4; nt++)
                    mma_tf32(acc[mt][nt], af, bf[nt]);
            }
        }
        __syncthreads();
    }

#pragma unroll
    for (int mt = 0; mt < 4; mt++) {
        int r0 = mBase + wM * 64 + mt * 16 + g4;
        int r1 = r0 + 8;
#pragma unroll
        for (int nt = 0; nt < 4; nt++) {
            int n0 = nBase + wN * 32 + nt * 8 + t4 * 2;
            float2 bv = *(const float2*)(g_b0p + n0);
            *(float2*)(g_G0 + (size_t)r0 * G_ + n0) =
                make_float2(acc[mt][nt][0] + bv.x, acc[mt][nt][1] + bv.y);
            *(float2*)(g_G0 + (size_t)r1 * G_ + n0) =
                make_float2(acc[mt][nt][2] + bv.x, acc[mt][nt][3] + bv.y);
        }
    }
}

// ---------------- persistent recurrent kernel (fp16 m16n8k16 mma) ----------------
// Consumer warps 0..15: ks = w&7 (K-16th of 128-chunk), wm = w>>3 (prow half), N=64.
// Producer warp 16 (tid 512): 16 K=128 chunks/step into 5 stages (R14 parity).
// Chunks 0..7: {B=h0 img, A0=Wh0 frags, A1=Wx1 frags}; 8..15: {B=h1, A0=Wh1}.
// B image layout per chunk: [ks(8)][bt(8)][lane(32)] uint2 {b0,b1} (16 KB).
// h element (unit k within chunk = ks*16+kk, batch b): lane=(b&7)*4+((kk&7)>>1),
// bt=b>>3, reg=kk>>3, half=kk&1.

__global__ void __launch_bounds__(NTHR, 1) lstm_persist(float* __restrict__ out)
{
    extern __shared__ char sm[];
    float* sB = (float*)(sm + SM_BI);
    float* P  = (float*)sm;                       // partial buffer (overlay)
    const uint32_t smBase = (uint32_t)__cvta_generic_to_shared(sm);
    const uint32_t fullB  = smBase + SM_MB;
    const uint32_t emptyB = smBase + SM_MB + 40;

    const int c    = blockIdx.x;
    const int tid  = threadIdx.x;
    const int w    = tid >> 5;
    const int lane = tid & 31;
    const int ks   = w & 7;          // consumer K-16th
    const int wm   = (w >> 3) & 1;   // prow half
    const int g4   = lane >> 2;
    const int t4   = lane & 3;
    const int v    = tid & 7;        // unit within CTA (consumers)
    const int b    = tid >> 3;       // batch (consumers, <64)
    const int u    = c * 8 + v;
    // h-image index for (u, b)
    const int ch_h = u >> 7;
    const int kl_h = u & 127;
    const int ks_h = kl_h >> 4;
    const int kk_h = kl_h & 15;
    const int fidx = ((((ch_h * 8 + ks_h) * 8 + (b >> 3)) * 32
                       + ((b & 7) * 4 + ((kk_h & 7) >> 1))) * 4)
                     + ((kk_h >> 3) * 2) + (kk_h & 1);

    if (tid == 0) {
#pragma unroll
        for (int s = 0; s < NSTG; s++) {
            mbar_init(fullB  + s * 8, 1);
            mbar_init(emptyB + s * 8, 16);
        }
    }
    if (tid < 32) sB[tid] = g_b1p[c * 32 + tid];
    asm volatile("fence.proxy.async.shared::cta;" ::: "memory");
    __syncthreads();

    float c0r = 0.f, c1r = 0.f;

    // preamble: h0[0] from G0[0] (h=0), zero h1[-1]
    if (tid < NCONS) {
        __half* h0w0 = g_h0I[0];
        __half* h1w0 = g_h1I[0];
        size_t gbase = (size_t)b * G_ + c * 32;
        float gi = g_G0[gbase + v];
        float go = g_G0[gbase + 16 + v];
        float gg = g_G0[gbase + 24 + v];
        float cn = sigmoidf_(gi) * tanhf(gg);
        float hn = sigmoidf_(go) * tanhf(cn);
        c0r = cn;
        h0w0[fidx] = __float2half(hn);
        h1w0[fidx] = __float2half(0.f);
    }
    gsync();

    const uint4* a0B = g_A0f + (size_t)c * (8 * 512);
    const uint4* a1B = g_A1f + (size_t)c * (8 * 512);
    const uint4* a2B = g_A2f + (size_t)c * (8 * 512);

    for (int t = 0; t < S_; t++) {
        const __half* bH0 = g_h0I[t & 1];          // h0[t]
        __half*       wH0 = g_h0I[(t + 1) & 1];
        const __half* bH1 = g_h1I[t & 1];          // h1[t-1]
        __half*       wH1 = g_h1I[(t + 1) & 1];

        // consumers: prefetch next layer0's G0 operands
        float p_gi = 0.f, p_gf = 0.f, p_go = 0.f, p_gg = 0.f;
        if (tid < NCONS && t + 1 < S_) {
            size_t gb = ((size_t)(t + 1) * B_ + b) * G_ + c * 32;
            p_gi = g_G0[gb + v];
            p_gf = g_G0[gb + 8 + v];
            p_go = g_G0[gb + 16 + v];
            p_gg = g_G0[gb + 24 + v];
        }

        float acc0[8][4], acc1[8][4];
#pragma unroll
        for (int bt = 0; bt < 8; bt++)
#pragma unroll
            for (int e = 0; e < 4; e++) { acc0[bt][e] = 0.f; acc1[bt][e] = 0.f; }

        if (tid == NCONS) {
            // ---------------- producer ----------------
            for (int ch = 0; ch < 16; ch++) {
                int s = ch % 5, n = ch / 5;
                if (t > 0 || n > 0) {
                    uint32_t par = (uint32_t)((((s != 0) ? (t & 1) : 0) + n + 1) & 1);
                    mbar_wait(emptyB + s * 8, par);
                }
                uint32_t sb = smBase + (uint32_t)s * STG_SZ;
                uint32_t fb = fullB + s * 8;
                if (ch < 8) {
                    mbar_expect_tx(fb, 32768u);
                    bulk_g2s(sb,          bH0 + (size_t)ch * 8192, 16384, fb);
                    bulk_g2s(sb + 16384,  a0B + (size_t)ch * 512,  8192,  fb);
                    bulk_g2s(sb + 24576,  a1B + (size_t)ch * 512,  8192,  fb);
                } else {
                    int cc = ch - 8;
                    mbar_expect_tx(fb, 24576u);
                    bulk_g2s(sb,          bH1 + (size_t)cc * 8192, 16384, fb);
                    bulk_g2s(sb + 16384,  a2B + (size_t)cc * 512,  8192,  fb);
                }
            }
        } else if (tid < NCONS) {
            // ---------------- consumers ----------------
            // chunks 0..7 : Wh0 -> acc0, Wx1 -> acc1  (B = h0[t])
            for (int ch = 0; ch < 8; ch++) {
                int s = ch % 5, n = ch / 5;
                uint32_t par = (uint32_t)((((s != 0) ? (t & 1) : 0) + n) & 1);
                mbar_wait(fullB + s * 8, par);
                const char* st = sm + s * STG_SZ;
                const uint4* A0f = (const uint4*)(st + 16384);
                const uint4* A1f = (const uint4*)(st + 24576);
                const uint2* Bf  = (const uint2*)st;
                int aidx = (wm * 8 + ks) * 32 + lane;
                uint4 a0 = A0f[aidx];
                uint4 a1 = A1f[aidx];
#pragma unroll
                for (int bt = 0; bt < 8; bt++) {
                    uint2 bv = Bf[(ks * 8 + bt) * 32 + lane];
                    mma_f16(acc0[bt], a0, bv);
                    mma_f16(acc1[bt], a1, bv);
                }
                if (lane == 0) mbar_arrive(emptyB + s * 8);
            }
            // chunks 8..15 : Wh1 -> acc1  (B = h1[t-1])
            for (int ch = 8; ch < 16; ch++) {
                int s = ch % 5, n = ch / 5;
                uint32_t par = (uint32_t)((((s != 0) ? (t & 1) : 0) + n) & 1);
                mbar_wait(fullB + s * 8, par);
                const char* st = sm + s * STG_SZ;
                const uint4* A0f = (const uint4*)(st + 16384);
                const uint2* Bf  = (const uint2*)st;
                int aidx = (wm * 8 + ks) * 32 + lane;
                uint4 a0 = A0f[aidx];
#pragma unroll
                for (int bt = 0; bt < 8; bt++) {
                    uint2 bv = Bf[(ks * 8 + bt) * 32 + lane];
                    mma_f16(acc1[bt], a0, bv);
                }
                if (lane == 0) mbar_arrive(emptyB + s * 8);
            }
        }
        __syncthreads();   // all stages consumed; safe to overlay partials

        // ---- write K-split partials (row stride 68 floats, 4352 floats per ks) ----
        if (tid < NCONS) {
            int r0 = wm * 16 + g4;
            int base0 = ks * 4352;
#pragma unroll
            for (int bt = 0; bt < 8; bt++) {
                int col = bt * 8 + t4 * 2;
                *(float2*)&P[base0 + r0 * 68 + col]        = make_float2(acc0[bt][0], acc0[bt][1]);
                *(float2*)&P[base0 + (r0 + 8) * 68 + col]  = make_float2(acc0[bt][2], acc0[bt][3]);
                *(float2*)&P[base0 + 2176 + r0 * 68 + col]       = make_float2(acc1[bt][0], acc1[bt][1]);
                *(float2*)&P[base0 + 2176 + (r0 + 8) * 68 + col] = make_float2(acc1[bt][2], acc1[bt][3]);
            }
        }
        __syncthreads();

        // ---- reduce 8 partials + cell epilogues ----
        if (tid < NCONS) {
            float g0[4], g1[4];
#pragma unroll
            for (int q = 0; q < 4; q++) {
                int row = q * 8 + v;
                float s0 = 0.f, s1 = 0.f;
#pragma unroll
                for (int kr = 0; kr < 8; kr++) {
                    s0 += P[kr * 4352 + row * 68 + b];
                    s1 += P[kr * 4352 + 2176 + row * 68 + b];
                }
                g0[q] = s0; g1[q] = s1;
            }
            // layer 1 step t
            {
                float gi = g1[0] + sB[v];
                float gf = g1[1] + sB[8 + v];
                float go = g1[2] + sB[16 + v];
                float gg = g1[3] + sB[24 + v];
                float cn = sigmoidf_(gf) * c1r + sigmoidf_(gi) * tanhf(gg);
                float hn = sigmoidf_(go) * tanhf(cn);
                c1r = cn;
                out[((size_t)b * S_ + t) * H_ + u] = hn;
                wH1[fidx] = __float2half(hn);
                if (t == S_ - 1) {
                    out[(size_t)OUT_ELEMS + 1ull * BH_ + (size_t)b * H_ + u] = hn;
                    out[(size_t)OUT_ELEMS + 3ull * BH_ + (size_t)b * H_ + u] = cn;
                }
            }
            // layer 0 step t+1
            if (t < S_ - 1) {
                float gi = g0[0] + p_gi;
                float gf = g0[1] + p_gf;
                float go = g0[2] + p_go;
                float gg = g0[3] + p_gg;
                float cn = sigmoidf_(gf) * c0r + sigmoidf_(gi) * tanhf(gg);
                float hn = sigmoidf_(go) * tanhf(cn);
                c0r = cn;
                wH0[fidx] = __float2half(hn);
                if (t == S_ - 2) {
                    out[(size_t)OUT_ELEMS + (size_t)b * H_ + u]              = hn;
                    out[(size_t)OUT_ELEMS + 2ull * BH_ + (size_t)b * H_ + u] = cn;
                }
            }
        }
        if (t + 1 < S_) gsync();
    }
}

// ---------------- launch ----------------
extern "C" void kernel_launch(void* const* d_in, const int* in_sizes, int n_in,
                              void* d_out, int out_size)
{
    const float* x   = (const float*)d_in[0];
    const float* Wx0 = (const float*)d_in[1];
    const float* Wh0 = (const float*)d_in[2];
    const float* bx0 = (const float*)d_in[3];
    const float* bh0 = (const float*)d_in[4];
    const float* Wx1 = (const float*)d_in[5];
    const float* Wh1 = (const float*)d_in[6];
    const float* bx1 = (const float*)d_in[7];
    const float* bh1 = (const float*)d_in[8];
    float* out = (float*)d_out;

    static bool attr_done = false;
    if (!attr_done) {
        cudaFuncSetAttribute(lstm_persist,
                             cudaFuncAttributeMaxDynamicSharedMemorySize, SM_TOT);
        attr_done = true;
    }

    convert_nat<<<2048, 256>>>(Wx0, bx0, bh0, bx1, bh1);
    convert_frag<<<4096, 256>>>(Wh0, Wx1, Wh1);
    init_kernel<<<1, 32>>>();
    precompute_kernel<<<dim3(G_ / 128, (S_ * B_) / 128), 256>>>(x);
    lstm_persist<<<NCTA, NTHR, SM_TOT>>>(out);
}

// round 16
// speedup vs baseline: 1.4379x; 1.1093x over previous
#include <cuda_runtime.h>
#include <cuda_fp16.h>
#include <cstdint>

// Problem dims
#define B_  64
#define S_  512
#define I_  512
#define H_  1024
#define G_  4096          // 4*H
#define BH_ (B_*H_)       // 65536
#define OUT_ELEMS (B_*S_*H_)   // 33554432

#define NCTA  128
#define NTHR  544         // 512 consumers + 32 producer warp
#define NCONS 512

// persistent-kernel smem plan (pinned Wh0/Wx1 + 3-stage ring)
// [0,65536)        : pinned Wh0 fragments (8 chunks x 8KB)
// [65536,131072)   : pinned Wx1 fragments
// [131072,204800)  : ring, 3 stages x 24576 (B(h) @ +0 16KB, Wh1 frags @ +16384 8KB)
// partial buffer (69632 B) overlays the ring after consumption
#define SM_W0   0
#define SM_W1   65536
#define SM_RING 131072
#define STG_SZ  24576
#define NSTG    3
#define SM_BI   204800
#define SM_MB   204928    // full[3] @ +0, empty[3] @ +24, pin @ +48
#define SM_TOT  204992

// ---------------- device scratch (static, allowed) ----------------
__device__ float  g_Wx0p[G_*I_];            // tf32-rounded, gate-permuted rows (for precompute)
__device__ float  g_b0p[G_];                // bx0+bh0, permuted (folded into G0)
__device__ float  g_b1p[G_];                // bx1+bh1, permuted
// fp16 k16-fragment weights: [c][ch(8)][frag(512)] uint4 (8MB each)
__device__ uint4  g_A0f[(size_t)NCTA*8*512];   // Wh0
__device__ uint4  g_A1f[(size_t)NCTA*8*512];   // Wx1
__device__ uint4  g_A2f[(size_t)NCTA*8*512];   // Wh1
__device__ float  g_G0[(size_t)S_*B_*G_];   // x-path preactivations [t][b][prow] (512MB)
__device__ __half g_h0I[2][65536];          // h0 B-fragment image fp16, double buffered
__device__ __half g_h1I[2][65536];          // h1 image
__device__ unsigned g_barCount;
__device__ volatile unsigned g_barGen;

// ---------------- helpers ----------------
__device__ __forceinline__ float f2tf_f(float f) {
    uint32_t r;
    asm("cvt.rna.tf32.f32 %0, %1;" : "=r"(r) : "f"(f));
    return __uint_as_float(r);
}

// legacy tf32 mma (precompute kernel only)
__device__ __forceinline__ void mma_tf32(float* d, float4 a, float2 b) {
    asm volatile(
        "mma.sync.aligned.m16n8k8.row.col.f32.tf32.tf32.f32 "
        "{%0,%1,%2,%3}, {%4,%5,%6,%7}, {%8,%9}, {%0,%1,%2,%3};\n"
        : "+f"(d[0]), "+f"(d[1]), "+f"(d[2]), "+f"(d[3])
        : "r"(__float_as_uint(a.x)), "r"(__float_as_uint(a.y)),
          "r"(__float_as_uint(a.z)), "r"(__float_as_uint(a.w)),
          "r"(__float_as_uint(b.x)), "r"(__float_as_uint(b.y)));
}

// fp16 m16n8k16 mma, fp32 accumulate
__device__ __forceinline__ void mma_f16(float* d, uint4 a, uint2 b) {
    asm volatile(
        "mma.sync.aligned.m16n8k16.row.col.f32.f16.f16.f32 "
        "{%0,%1,%2,%3}, {%4,%5,%6,%7}, {%8,%9}, {%0,%1,%2,%3};\n"
        : "+f"(d[0]), "+f"(d[1]), "+f"(d[2]), "+f"(d[3])
        : "r"(a.x), "r"(a.y), "r"(a.z), "r"(a.w), "r"(b.x), "r"(b.y));
}

__device__ __forceinline__ float sigmoidf_(float x) { return 1.0f / (1.0f + expf(-x)); }

// ---- TMA bulk + mbarrier machinery ----
__device__ __forceinline__ void mbar_init(uint32_t addr, uint32_t count) {
    asm volatile("mbarrier.init.shared.b64 [%0], %1;" :: "r"(addr), "r"(count) : "memory");
}
__device__ __forceinline__ void mbar_expect_tx(uint32_t addr, uint32_t bytes) {
    asm volatile("mbarrier.arrive.expect_tx.shared.b64 _, [%0], %1;"
                 :: "r"(addr), "r"(bytes) : "memory");
}
__device__ __forceinline__ void mbar_arrive(uint32_t addr) {
    asm volatile("mbarrier.arrive.shared.b64 _, [%0];" :: "r"(addr) : "memory");
}
__device__ __forceinline__ void bulk_g2s(uint32_t dst, const void* src,
                                         uint32_t bytes, uint32_t mbar) {
    asm volatile(
        "cp.async.bulk.shared::cta.global.mbarrier::complete_tx::bytes [%0], [%1], %2, [%3];"
        :: "r"(dst), "l"(src), "r"(bytes), "r"(mbar) : "memory");
}
__device__ __forceinline__ void mbar_wait(uint32_t mbar, uint32_t parity) {
    asm volatile(
        "{\n\t"
        ".reg .pred P;\n\t"
        "WAIT_LOOP_%=:\n\t"
        "mbarrier.try_wait.parity.acquire.cta.shared::cta.b64 P, [%0], %1, 0x989680;\n\t"
        "@P bra.uni WAIT_DONE_%=;\n\t"
        "bra.uni WAIT_LOOP_%=;\n\t"
        "WAIT_DONE_%=:\n\t"
        "}"
        :: "r"(mbar), "r"(parity) : "memory");
}

// grid barrier (all NCTA CTAs co-resident) — proven atomic version
__device__ __forceinline__ void gsync() {
    __syncthreads();
    if (threadIdx.x == 0) {
        unsigned gen = g_barGen;
        __threadfence();
        if (atomicAdd(&g_barCount, 1u) == NCTA - 1) {
            g_barCount = 0;
            __threadfence();
            g_barGen = gen + 1;
        } else {
            while (g_barGen == gen) { }
            __threadfence();
        }
    }
    __syncthreads();
}

// Row permutation: local row p (0..31) of CTA c: gate q = p>>3, unit v = p&7,
// original row = q*H + c*8 + v.

// ---------------- convert: natural Wx0 + biases ----------------
__global__ void __launch_bounds__(256) convert_nat(
    const float* __restrict__ Wx0, const float* __restrict__ bx0, const float* __restrict__ bh0,
    const float* __restrict__ bx1, const float* __restrict__ bh1)
{
    const int total = G_ * I_;
    for (int i = blockIdx.x * blockDim.x + threadIdx.x; i < total;
         i += gridDim.x * blockDim.x) {
        int prow = i / I_;
        int k    = i - prow * I_;
        int u    = ((prow >> 5) << 3) + (prow & 7);
        int q    = (prow >> 3) & 3;
        int orig = q * H_ + u;
        g_Wx0p[i] = f2tf_f(Wx0[(size_t)orig * I_ + k]);
        if (k == 0) {
            g_b0p[prow] = bx0[orig] + bh0[orig];
            g_b1p[prow] = bx1[orig] + bh1[orig];
        }
    }
}

// ---------------- convert: k16-fragment fp16 recurrent weights ----------------
// frag f = wm*256 + ks*32 + lane within a chunk; uint4 {a0,a1,a2,a3}:
//   p0 = wm*16 + (lane>>2); p1 = p0+8; k = ks*16 + (lane&3)*2
__global__ void __launch_bounds__(256) convert_frag(
    const float* __restrict__ Wh0, const float* __restrict__ Wx1, const float* __restrict__ Wh1)
{
    const int total = NCTA * 8 * 512;
    for (int idx = blockIdx.x * blockDim.x + threadIdx.x; idx < total;
         idx += gridDim.x * blockDim.x) {
        int lane = idx & 31;
        int ks   = (idx >> 5) & 7;
        int wm   = (idx >> 8) & 1;
        int ch   = (idx >> 9) & 7;
        int c    = idx >> 12;
        int p0 = wm * 16 + (lane >> 2);
        int p1 = p0 + 8;
        int q0 = p0 >> 3, v0 = p0 & 7;
        int q1 = p1 >> 3, v1 = p1 & 7;
        size_t o0 = (size_t)(q0 * H_ + c * 8 + v0) * H_;
        size_t o1 = (size_t)(q1 * H_ + c * 8 + v1) * H_;
        int k  = ch * 128 + ks * 16 + (lane & 3) * 2;
        uint4 w; __half2 h;
        #define PACK(W, dst) \
            h = __floats2half2_rn(W[o0 + k],     W[o0 + k + 1]); dst.x = *(uint32_t*)&h; \
            h = __floats2half2_rn(W[o1 + k],     W[o1 + k + 1]); dst.y = *(uint32_t*)&h; \
            h = __floats2half2_rn(W[o0 + k + 8], W[o0 + k + 9]); dst.z = *(uint32_t*)&h; \
            h = __floats2half2_rn(W[o1 + k + 8], W[o1 + k + 9]); dst.w = *(uint32_t*)&h;
        PACK(Wh0, w); g_A0f[idx] = w;
        PACK(Wx1, w); g_A1f[idx] = w;
        PACK(Wh1, w); g_A2f[idx] = w;
        #undef PACK
    }
}

// ---------------- init (every replay): barrier state only ----------------
__global__ void init_kernel() {
    if (threadIdx.x == 0) { g_barCount = 0; g_barGen = 0; }
}

// ---------------- x-path precompute: G0 = x@Wx0p^T + b0p ----------------
__global__ void __launch_bounds__(256, 1) precompute_kernel(const float* __restrict__ x)
{
    __shared__ float As[128][20];
    __shared__ float Bs[128][20];

    const int tid  = threadIdx.x;
    const int w    = tid >> 5;
    const int lane = tid & 31;
    const int wM   = w >> 2;
    const int wN   = w & 3;
    const int mBase = blockIdx.y * 128;
    const int nBase = blockIdx.x * 128;
    const int g4 = lane >> 2;
    const int t4 = lane & 3;

    float acc[4][4][4];
#pragma unroll
    for (int mt = 0; mt < 4; mt++)
#pragma unroll
        for (int nt = 0; nt < 4; nt++)
#pragma unroll
            for (int e = 0; e < 4; e++) acc[mt][nt][e] = 0.0f;

    for (int kc = 0; kc < I_; kc += 16) {
#pragma unroll
        for (int it = 0; it < 2; it++) {
            int i  = tid + it * 256;
            int r  = i >> 2;
            int c4 = (i & 3) * 4;
            int m  = mBase + r;
            int tt = m >> 6;
            int bb = m & 63;
            float4 v = *(const float4*)(x + ((size_t)bb * S_ + tt) * I_ + kc + c4);
            As[r][c4 + 0] = f2tf_f(v.x); As[r][c4 + 1] = f2tf_f(v.y);
            As[r][c4 + 2] = f2tf_f(v.z); As[r][c4 + 3] = f2tf_f(v.w);
        }
#pragma unroll
        for (int it = 0; it < 2; it++) {
            int i  = tid + it * 256;
            int r  = i >> 2;
            int c4 = (i & 3) * 4;
            float4 v = *(const float4*)(g_Wx0p + (size_t)(nBase + r) * I_ + kc + c4);
            Bs[r][c4 + 0] = v.x; Bs[r][c4 + 1] = v.y;
            Bs[r][c4 + 2] = v.z; Bs[r][c4 + 3] = v.w;
        }
        __syncthreads();

#pragma unroll
        for (int kk = 0; kk < 2; kk++) {
            int k = kk * 8;
            float2 bf[4];
#pragma unroll
            for (int nt = 0; nt < 4; nt++) {
                int n = wN * 32 + nt * 8 + g4;
                bf[nt] = make_float2(Bs[n][k + t4], Bs[n][k + t4 + 4]);
            }
#pragma unroll
            for (int mt = 0; mt < 4; mt++) {
                int r = wM * 64 + mt * 16 + g4;
                float4 af = make_float4(As[r][k + t4], As[r + 8][k + t4],
                                        As[r][k + t4 + 4], As[r + 8][k + t4 + 4]);
#pragma unroll
                for (int nt = 0; nt < 4; nt++)
                    mma_tf32(acc[mt][nt], af, bf[nt]);
            }
        }
        __syncthreads();
    }

#pragma unroll
    for (int mt = 0; mt < 4; mt++) {
        int r0 = mBase + wM * 64 + mt * 16 + g4;
        int r1 = r0 + 8;
#pragma unroll
        for (int nt = 0; nt < 4; nt++) {
            int n0 = nBase + wN * 32 + nt * 8 + t4 * 2;
            float2 bv = *(const float2*)(g_b0p + n0);
            *(float2*)(g_G0 + (size_t)r0 * G_ + n0) =
                make_float2(acc[mt][nt][0] + bv.x, acc[mt][nt][1] + bv.y);
            *(float2*)(g_G0 + (size_t)r1 * G_ + n0) =
                make_float2(acc[mt][nt][2] + bv.x, acc[mt][nt][3] + bv.y);
        }
    }
}

// ---------------- persistent recurrent kernel (pinned weights + fp16 mma) ----
// Consumer warps 0..15: ks4 = w&3 (K-quarter: 2 k16-subs), wm = (w>>2)&1 (prow
// half), wb = (w>>3)&1 (batch half: 4 bt). Producer warp 16 (tid 512).
// Chunks 0..7: stage h0 only (16 KB); Wh0/Wx1 read from pinned SMEM.
// Chunks 8..15: stage {h1 16KB, Wh1 frags 8KB}. 3-stage ring, R6 parity.

__global__ void __launch_bounds__(NTHR, 1) lstm_persist(float* __restrict__ out)
{
    extern __shared__ char sm[];
    float* sB = (float*)(sm + SM_BI);
    float* P  = (float*)(sm + SM_RING);           // partial buffer (ring overlay)
    const uint32_t smBase = (uint32_t)__cvta_generic_to_shared(sm);
    const uint32_t fullB  = smBase + SM_MB;
    const uint32_t emptyB = smBase + SM_MB + 24;
    const uint32_t pinB   = smBase + SM_MB + 48;

    const int c    = blockIdx.x;
    const int tid  = threadIdx.x;
    const int w    = tid >> 5;
    const int lane = tid & 31;
    const int ks4  = w & 3;          // consumer K-quarter
    const int wm   = (w >> 2) & 1;   // prow half
    const int wb   = (w >> 3) & 1;   // batch half
    const int g4   = lane >> 2;
    const int t4   = lane & 3;
    const int v    = tid & 7;        // unit within CTA (consumers)
    const int b    = tid >> 3;       // batch (consumers, <64)
    const int u    = c * 8 + v;
    // h-image index for (u, b): chunk ch_h = u>>7, ksub = (u>>4)&7, kk = u&15
    const int ch_h = u >> 7;
    const int ks_h = (u >> 4) & 7;
    const int kk_h = u & 15;
    const int fidx = ((((ch_h * 8 + ks_h) * 8 + (b >> 3)) * 32
                       + ((b & 7) * 4 + ((kk_h & 7) >> 1))) * 4)
                     + ((kk_h >> 3) * 2) + (kk_h & 1);

    if (tid == 0) {
#pragma unroll
        for (int s = 0; s < NSTG; s++) {
            mbar_init(fullB  + s * 8, 1);
            mbar_init(emptyB + s * 8, 16);
        }
        mbar_init(pinB, 1);
    }
    if (tid < 32) sB[tid] = g_b1p[c * 32 + tid];
    asm volatile("fence.proxy.async.shared::cta;" ::: "memory");
    __syncthreads();

    // load pinned Wh0/Wx1 fragments (once)
    if (tid == 0) {
        mbar_expect_tx(pinB, 131072u);
        const uint4* w0 = g_A0f + (size_t)c * 4096;
        const uint4* w1 = g_A1f + (size_t)c * 4096;
#pragma unroll
        for (int i = 0; i < 4; i++) {
            bulk_g2s(smBase + SM_W0 + i * 16384, w0 + i * 1024, 16384, pinB);
            bulk_g2s(smBase + SM_W1 + i * 16384, w1 + i * 1024, 16384, pinB);
        }
    }

    float c0r = 0.f, c1r = 0.f;

    // preamble: h0[0] from G0[0] (h=0), zero h1[-1]
    if (tid < NCONS) {
        __half* h0w0 = g_h0I[0];
        __half* h1w0 = g_h1I[0];
        size_t gbase = (size_t)b * G_ + c * 32;
        float gi = g_G0[gbase + v];
        float go = g_G0[gbase + 16 + v];
        float gg = g_G0[gbase + 24 + v];
        float cn = sigmoidf_(gi) * tanhf(gg);
        float hn = sigmoidf_(go) * tanhf(cn);
        c0r = cn;
        h0w0[fidx] = __float2half(hn);
        h1w0[fidx] = __float2half(0.f);
    }
    mbar_wait(pinB, 0);
    gsync();

    const uint4* a2B = g_A2f + (size_t)c * (8 * 512);
    const uint4* W0p = (const uint4*)(sm + SM_W0);
    const uint4* W1p = (const uint4*)(sm + SM_W1);

    for (int t = 0; t < S_; t++) {
        const __half* bH0 = g_h0I[t & 1];          // h0[t]
        __half*       wH0 = g_h0I[(t + 1) & 1];
        const __half* bH1 = g_h1I[t & 1];          // h1[t-1]
        __half*       wH1 = g_h1I[(t + 1) & 1];

        // consumers: prefetch next layer0's G0 operands
        float p_gi = 0.f, p_gf = 0.f, p_go = 0.f, p_gg = 0.f;
        if (tid < NCONS && t + 1 < S_) {
            size_t gb = ((size_t)(t + 1) * B_ + b) * G_ + c * 32;
            p_gi = g_G0[gb + v];
            p_gf = g_G0[gb + 8 + v];
            p_go = g_G0[gb + 16 + v];
            p_gg = g_G0[gb + 24 + v];
        }

        float acc0[4][4], acc1[4][4];
#pragma unroll
        for (int bt = 0; bt < 4; bt++)
#pragma unroll
            for (int e = 0; e < 4; e++) { acc0[bt][e] = 0.f; acc1[bt][e] = 0.f; }

        if (tid == NCONS) {
            // ---------------- producer ----------------
            for (int ch = 0; ch < 16; ch++) {
                int s = ch % 3, n = ch / 3;
                if (t > 0 || ch >= 3) {
                    uint32_t par = (uint32_t)((((s != 0) ? (t & 1) : 0) + n + 1) & 1);
                    mbar_wait(emptyB + s * 8, par);
                }
                uint32_t sb = smBase + SM_RING + (uint32_t)s * STG_SZ;
                uint32_t fb = fullB + s * 8;
                if (ch < 8) {
                    mbar_expect_tx(fb, 16384u);
                    bulk_g2s(sb, bH0 + (size_t)ch * 8192, 16384, fb);
                } else {
                    int cc = ch - 8;
                    mbar_expect_tx(fb, 24576u);
                    bulk_g2s(sb,          bH1 + (size_t)cc * 8192, 16384, fb);
                    bulk_g2s(sb + 16384,  a2B + (size_t)cc * 512,  8192,  fb);
                }
            }
        } else if (tid < NCONS) {
            // ---------------- consumers ----------------
            // chunks 0..7 : pinned Wh0 -> acc0, pinned Wx1 -> acc1  (B = h0[t])
            for (int ch = 0; ch < 8; ch++) {
                int s = ch % 3, n = ch / 3;
                uint32_t par = (uint32_t)((((s != 0) ? (t & 1) : 0) + n) & 1);
                mbar_wait(fullB + s * 8, par);
                const uint2* Bf = (const uint2*)(sm + SM_RING + s * STG_SZ);
                const uint4* A0f = W0p + ch * 512;
                const uint4* A1f = W1p + ch * 512;
#pragma unroll
                for (int j = 0; j < 2; j++) {
                    int ksub = ks4 * 2 + j;
                    int aidx = (wm * 8 + ksub) * 32 + lane;
                    uint4 a0 = A0f[aidx];
                    uint4 a1 = A1f[aidx];
#pragma unroll
                    for (int bt = 0; bt < 4; bt++) {
                        uint2 bv = Bf[(ksub * 8 + wb * 4 + bt) * 32 + lane];
                        mma_f16(acc0[bt], a0, bv);
                        mma_f16(acc1[bt], a1, bv);
                    }
                }
                if (lane == 0) mbar_arrive(emptyB + s * 8);
            }
            // chunks 8..15 : staged Wh1 -> acc1  (B = h1[t-1])
            for (int ch = 8; ch < 16; ch++) {
                int s = ch % 3, n = ch / 3;
                uint32_t par = (uint32_t)((((s != 0) ? (t & 1) : 0) + n) & 1);
                mbar_wait(fullB + s * 8, par);
                const char* st = sm + SM_RING + s * STG_SZ;
                const uint2* Bf  = (const uint2*)st;
                const uint4* A0f = (const uint4*)(st + 16384);
#pragma unroll
                for (int j = 0; j < 2; j++) {
                    int ksub = ks4 * 2 + j;
                    int aidx = (wm * 8 + ksub) * 32 + lane;
                    uint4 a0 = A0f[aidx];
#pragma unroll
                    for (int bt = 0; bt < 4; bt++) {
                        uint2 bv = Bf[(ksub * 8 + wb * 4 + bt) * 32 + lane];
                        mma_f16(acc1[bt], a0, bv);
                    }
                }
                if (lane == 0) mbar_arrive(emptyB + s * 8);
            }
        }
        __syncthreads();   // all stages consumed; safe to overlay partials

        // ---- write K-split partials (4 splits x 4352 floats: [mat][row(32)x68]) ----
        if (tid < NCONS) {
            int r0 = wm * 16 + g4;
            int base0 = ks4 * 4352;
#pragma unroll
            for (int bt = 0; bt < 4; bt++) {
                int col = wb * 32 + bt * 8 + t4 * 2;
                *(float2*)&P[base0 + r0 * 68 + col]        = make_float2(acc0[bt][0], acc0[bt][1]);
                *(float2*)&P[base0 + (r0 + 8) * 68 + col]  = make_float2(acc0[bt][2], acc0[bt][3]);
                *(float2*)&P[base0 + 2176 + r0 * 68 + col]       = make_float2(acc1[bt][0], acc1[bt][1]);
                *(float2*)&P[base0 + 2176 + (r0 + 8) * 68 + col] = make_float2(acc1[bt][2], acc1[bt][3]);
            }
        }
        __syncthreads();

        // ---- reduce 4 partials + cell epilogues ----
        if (tid < NCONS) {
            float g0[4], g1[4];
#pragma unroll
            for (int q = 0; q < 4; q++) {
                int row = q * 8 + v;
                float s0 = 0.f, s1 = 0.f;
#pragma unroll
                for (int kr = 0; kr < 4; kr++) {
                    s0 += P[kr * 4352 + row * 68 + b];
                    s1 += P[kr * 4352 + 2176 + row * 68 + b];
                }
                g0[q] = s0; g1[q] = s1;
            }
            // layer 1 step t
            {
                float gi = g1[0] + sB[v];
                float gf = g1[1] + sB[8 + v];
                float go = g1[2] + sB[16 + v];
                float gg = g1[3] + sB[24 + v];
                float cn = sigmoidf_(gf) * c1r + sigmoidf_(gi) * tanhf(gg);
                float hn = sigmoidf_(go) * tanhf(cn);
                c1r = cn;
                out[((size_t)b * S_ + t) * H_ + u] = hn;
                wH1[fidx] = __float2half(hn);
                if (t == S_ - 1) {
                    out[(size_t)OUT_ELEMS + 1ull * BH_ + (size_t)b * H_ + u] = hn;
                    out[(size_t)OUT_ELEMS + 3ull * BH_ + (size_t)b * H_ + u] = cn;
                }
            }
            // layer 0 step t+1
            if (t < S_ - 1) {
                float gi = g0[0] + p_gi;
                float gf = g0[1] + p_gf;
                float go = g0[2] + p_go;
                float gg = g0[3] + p_gg;
                float cn = sigmoidf_(gf) * c0r + sigmoidf_(gi) * tanhf(gg);
                float hn = sigmoidf_(go) * tanhf(cn);
                c0r = cn;
                wH0[fidx] = __float2half(hn);
                if (t == S_ - 2) {
                    out[(size_t)OUT_ELEMS + (size_t)b * H_ + u]              = hn;
                    out[(size_t)OUT_ELEMS + 2ull * BH_ + (size_t)b * H_ + u] = cn;
                }
            }
        }
        if (t + 1 < S_) gsync();
    }
}

// ---------------- launch ----------------
extern "C" void kernel_launch(void* const* d_in, const int* in_sizes, int n_in,
                              void* d_out, int out_size)
{
    const float* x   = (const float*)d_in[0];
    const float* Wx0 = (const float*)d_in[1];
    const float* Wh0 = (const float*)d_in[2];
    const float* bx0 = (const float*)d_in[3];
    const float* bh0 = (const float*)d_in[4];
    const float* Wx1 = (const float*)d_in[5];
    const float* Wh1 = (const float*)d_in[6];
    const float* bx1 = (const float*)d_in[7];
    const float* bh1 = (const float*)d_in[8];
    float* out = (float*)d_out;

    static bool attr_done = false;
    if (!attr_done) {
        cudaFuncSetAttribute(lstm_persist,
                             cudaFuncAttributeMaxDynamicSharedMemorySize, SM_TOT);
        attr_done = true;
    }

    convert_nat<<<2048, 256>>>(Wx0, bx0, bh0, bx1, bh1);
    convert_frag<<<4096, 256>>>(Wh0, Wx1, Wh1);
    init_kernel<<<1, 32>>>();
    precompute_kernel<<<dim3(G_ / 128, (S_ * B_) / 128), 256>>>(x);
    lstm_persist<<<NCTA, NTHR, SM_TOT>>>(out);
}

// round 17
// speedup vs baseline: 1.5365x; 1.0686x over previous
#include <cuda_runtime.h>
#include <cuda_fp16.h>
#include <cstdint>

// Problem dims
#define B_  64
#define S_  512
#define I_  512
#define H_  1024
#define G_  4096          // 4*H
#define BH_ (B_*H_)       // 65536
#define OUT_ELEMS (B_*S_*H_)   // 33554432

#define NCTA  128
#define NTHR  544         // 512 consumers + 32 producer warp
#define NCONS 512

// persistent-kernel smem plan (pinned Wh0/Wx1 + 2-stage ring of K=256 chunks)
// [0,65536)        : pinned Wh0 fragments (64KB)
// [65536,131072)   : pinned Wx1 fragments
// [131072,229376)  : ring, 2 stages x 49152 (B(h) 32KB @ +0, Wh1 frags 16KB @ +32768)
// partial buffer (69632 B) overlays the ring after consumption
#define SM_W0   0
#define SM_W1   65536
#define SM_RING 131072
#define STG_SZ  49152
#define NSTG    2
#define SM_BI   229376
#define SM_MB   229504    // full[2] @ +0, empty[2] @ +16, pin @ +32
#define SM_TOT  229568

// ---------------- device scratch (static, allowed) ----------------
__device__ float  g_Wx0p[G_*I_];            // tf32-rounded, gate-permuted rows (for precompute)
__device__ float  g_b0p[G_];                // bx0+bh0, permuted (folded into G0)
__device__ float  g_b1p[G_];                // bx1+bh1, permuted
// fp16 k16-fragment weights: [c][ch8][frag512] uint4 (8MB each)
__device__ uint4  g_A0f[(size_t)NCTA*8*512];   // Wh0
__device__ uint4  g_A1f[(size_t)NCTA*8*512];   // Wx1
__device__ uint4  g_A2f[(size_t)NCTA*8*512];   // Wh1
__device__ float  g_G0[(size_t)S_*B_*G_];   // x-path preactivations [t][b][prow] (512MB)
__device__ __half g_h0I[2][65536];          // h0 B-fragment image fp16, double buffered
__device__ __half g_h1I[2][65536];          // h1 image
__device__ unsigned g_barCount;
__device__ volatile unsigned g_barGen;

// ---------------- helpers ----------------
__device__ __forceinline__ float f2tf_f(float f) {
    uint32_t r;
    asm("cvt.rna.tf32.f32 %0, %1;" : "=r"(r) : "f"(f));
    return __uint_as_float(r);
}

// legacy tf32 mma (precompute kernel only)
__device__ __forceinline__ void mma_tf32(float* d, float4 a, float2 b) {
    asm volatile(
        "mma.sync.aligned.m16n8k8.row.col.f32.tf32.tf32.f32 "
        "{%0,%1,%2,%3}, {%4,%5,%6,%7}, {%8,%9}, {%0,%1,%2,%3};\n"
        : "+f"(d[0]), "+f"(d[1]), "+f"(d[2]), "+f"(d[3])
        : "r"(__float_as_uint(a.x)), "r"(__float_as_uint(a.y)),
          "r"(__float_as_uint(a.z)), "r"(__float_as_uint(a.w)),
          "r"(__float_as_uint(b.x)), "r"(__float_as_uint(b.y)));
}

// fp16 m16n8k16 mma, fp32 accumulate
__device__ __forceinline__ void mma_f16(float* d, uint4 a, uint2 b) {
    asm volatile(
        "mma.sync.aligned.m16n8k16.row.col.f32.f16.f16.f32 "
        "{%0,%1,%2,%3}, {%4,%5,%6,%7}, {%8,%9}, {%0,%1,%2,%3};\n"
        : "+f"(d[0]), "+f"(d[1]), "+f"(d[2]), "+f"(d[3])
        : "r"(a.x), "r"(a.y), "r"(a.z), "r"(a.w), "r"(b.x), "r"(b.y));
}

// fast transcendentals (error ~1e-6 rel — far below fp16/tf32 noise)
__device__ __forceinline__ float sigf(float x) {
    return __fdividef(1.0f, 1.0f + __expf(-x));
}
__device__ __forceinline__ float tanhfast(float x) {
    float xc = fminf(fmaxf(x, -15.0f), 15.0f);
    float e  = __expf(-2.0f * xc);
    return __fdividef(1.0f - e, 1.0f + e);
}

// ---- TMA bulk + mbarrier machinery ----
__device__ __forceinline__ void mbar_init(uint32_t addr, uint32_t count) {
    asm volatile("mbarrier.init.shared.b64 [%0], %1;" :: "r"(addr), "r"(count) : "memory");
}
__device__ __forceinline__ void mbar_expect_tx(uint32_t addr, uint32_t bytes) {
    asm volatile("mbarrier.arrive.expect_tx.shared.b64 _, [%0], %1;"
                 :: "r"(addr), "r"(bytes) : "memory");
}
__device__ __forceinline__ void mbar_arrive(uint32_t addr) {
    asm volatile("mbarrier.arrive.shared.b64 _, [%0];" :: "r"(addr) : "memory");
}
__device__ __forceinline__ void bulk_g2s(uint32_t dst, const void* src,
                                         uint32_t bytes, uint32_t mbar) {
    asm volatile(
        "cp.async.bulk.shared::cta.global.mbarrier::complete_tx::bytes [%0], [%1], %2, [%3];"
        :: "r"(dst), "l"(src), "r"(bytes), "r"(mbar) : "memory");
}
__device__ __forceinline__ void mbar_wait(uint32_t mbar, uint32_t parity) {
    asm volatile(
        "{\n\t"
        ".reg .pred P;\n\t"
        "WAIT_LOOP_%=:\n\t"
        "mbarrier.try_wait.parity.acquire.cta.shared::cta.b64 P, [%0], %1, 0x989680;\n\t"
        "@P bra.uni WAIT_DONE_%=;\n\t"
        "bra.uni WAIT_LOOP_%=;\n\t"
        "WAIT_DONE_%=:\n\t"
        "}"
        :: "r"(mbar), "r"(parity) : "memory");
}

// grid barrier (all NCTA CTAs co-resident) — proven atomic version
__device__ __forceinline__ void gsync() {
    __syncthreads();
    if (threadIdx.x == 0) {
        unsigned gen = g_barGen;
        __threadfence();
        if (atomicAdd(&g_barCount, 1u) == NCTA - 1) {
            g_barCount = 0;
            __threadfence();
            g_barGen = gen + 1;
        } else {
            while (g_barGen == gen) { }
            __threadfence();
        }
    }
    __syncthreads();
}

// Row permutation: local row p (0..31) of CTA c: gate q = p>>3, unit v = p&7,
// original row = q*H + c*8 + v.

// ---------------- convert: natural Wx0 + biases ----------------
__global__ void __launch_bounds__(256) convert_nat(
    const float* __restrict__ Wx0, const float* __restrict__ bx0, const float* __restrict__ bh0,
    const float* __restrict__ bx1, const float* __restrict__ bh1)
{
    const int total = G_ * I_;
    for (int i = blockIdx.x * blockDim.x + threadIdx.x; i < total;
         i += gridDim.x * blockDim.x) {
        int prow = i / I_;
        int k    = i - prow * I_;
        int u    = ((prow >> 5) << 3) + (prow & 7);
        int q    = (prow >> 3) & 3;
        int orig = q * H_ + u;
        g_Wx0p[i] = f2tf_f(Wx0[(size_t)orig * I_ + k]);
        if (k == 0) {
            g_b0p[prow] = bx0[orig] + bh0[orig];
            g_b1p[prow] = bx1[orig] + bh1[orig];
        }
    }
}

// ---------------- convert: k16-fragment fp16 recurrent weights ----------------
__global__ void __launch_bounds__(256) convert_frag(
    const float* __restrict__ Wh0, const float* __restrict__ Wx1, const float* __restrict__ Wh1)
{
    const int total = NCTA * 8 * 512;
    for (int idx = blockIdx.x * blockDim.x + threadIdx.x; idx < total;
         idx += gridDim.x * blockDim.x) {
        int lane = idx & 31;
        int ks   = (idx >> 5) & 7;
        int wm   = (idx >> 8) & 1;
        int ch   = (idx >> 9) & 7;
        int c    = idx >> 12;
        int p0 = wm * 16 + (lane >> 2);
        int p1 = p0 + 8;
        int q0 = p0 >> 3, v0 = p0 & 7;
        int q1 = p1 >> 3, v1 = p1 & 7;
        size_t o0 = (size_t)(q0 * H_ + c * 8 + v0) * H_;
        size_t o1 = (size_t)(q1 * H_ + c * 8 + v1) * H_;
        int k  = ch * 128 + ks * 16 + (lane & 3) * 2;
        uint4 w; __half2 h;
        #define PACK(W, dst) \
            h = __floats2half2_rn(W[o0 + k],     W[o0 + k + 1]); dst.x = *(uint32_t*)&h; \
            h = __floats2half2_rn(W[o1 + k],     W[o1 + k + 1]); dst.y = *(uint32_t*)&h; \
            h = __floats2half2_rn(W[o0 + k + 8], W[o0 + k + 9]); dst.z = *(uint32_t*)&h; \
            h = __floats2half2_rn(W[o1 + k + 8], W[o1 + k + 9]); dst.w = *(uint32_t*)&h;
        PACK(Wh0, w); g_A0f[idx] = w;
        PACK(Wx1, w); g_A1f[idx] = w;
        PACK(Wh1, w); g_A2f[idx] = w;
        #undef PACK
    }
}

// ---------------- init (every replay): barrier state only ----------------
__global__ void init_kernel() {
    if (threadIdx.x == 0) { g_barCount = 0; g_barGen = 0; }
}

// ---------------- x-path precompute: G0 = x@Wx0p^T + b0p ----------------
__global__ void __launch_bounds__(256, 1) precompute_kernel(const float* __restrict__ x)
{
    __shared__ float As[128][20];
    __shared__ float Bs[128][20];

    const int tid  = threadIdx.x;
    const int w    = tid >> 5;
    const int lane = tid & 31;
    const int wM   = w >> 2;
    const int wN   = w & 3;
    const int mBase = blockIdx.y * 128;
    const int nBase = blockIdx.x * 128;
    const int g4 = lane >> 2;
    const int t4 = lane & 3;

    float acc[4][4][4];
#pragma unroll
    for (int mt = 0; mt < 4; mt++)
#pragma unroll
        for (int nt = 0; nt < 4; nt++)
#pragma unroll
            for (int e = 0; e < 4; e++) acc[mt][nt][e] = 0.0f;

    for (int kc = 0; kc < I_; kc += 16) {
#pragma unroll
        for (int it = 0; it < 2; it++) {
            int i  = tid + it * 256;
            int r  = i >> 2;
            int c4 = (i & 3) * 4;
            int m  = mBase + r;
            int tt = m >> 6;
            int bb = m & 63;
            float4 v = *(const float4*)(x + ((size_t)bb * S_ + tt) * I_ + kc + c4);
            As[r][c4 + 0] = f2tf_f(v.x); As[r][c4 + 1] = f2tf_f(v.y);
            As[r][c4 + 2] = f2tf_f(v.z); As[r][c4 + 3] = f2tf_f(v.w);
        }
#pragma unroll
        for (int it = 0; it < 2; it++) {
            int i  = tid + it * 256;
            int r  = i >> 2;
            int c4 = (i & 3) * 4;
            float4 v = *(const float4*)(g_Wx0p + (size_t)(nBase + r) * I_ + kc + c4);
            Bs[r][c4 + 0] = v.x; Bs[r][c4 + 1] = v.y;
            Bs[r][c4 + 2] = v.z; Bs[r][c4 + 3] = v.w;
        }
        __syncthreads();

#pragma unroll
        for (int kk = 0; kk < 2; kk++) {
            int k = kk * 8;
            float2 bf[4];
#pragma unroll
            for (int nt = 0; nt < 4; nt++) {
                int n = wN * 32 + nt * 8 + g4;
                bf[nt] = make_float2(Bs[n][k + t4], Bs[n][k + t4 + 4]);
            }
#pragma unroll
            for (int mt = 0; mt < 4; mt++) {
                int r = wM * 64 + mt * 16 + g4;
                float4 af = make_float4(As[r][k + t4], As[r + 8][k + t4],
                                        As[r][k + t4 + 4], As[r + 8][k + t4 + 4]);
#pragma unroll
                for (int nt = 0; nt < 4; nt++)
                    mma_tf32(acc[mt][nt], af, bf[nt]);
            }
        }
        __syncthreads();
    }

#pragma unroll
    for (int mt = 0; mt < 4; mt++) {
        int r0 = mBase + wM * 64 + mt * 16 + g4;
        int r1 = r0 + 8;
#pragma unroll
        for (int nt = 0; nt < 4; nt++) {
            int n0 = nBase + wN * 32 + nt * 8 + t4 * 2;
            float2 bv = *(const float2*)(g_b0p + n0);
            *(float2*)(g_G0 + (size_t)r0 * G_ + n0) =
                make_float2(acc[mt][nt][0] + bv.x, acc[mt][nt][1] + bv.y);
            *(float2*)(g_G0 + (size_t)r1 * G_ + n0) =
                make_float2(acc[mt][nt][2] + bv.x, acc[mt][nt][3] + bv.y);
        }
    }
}

// ---------------- persistent recurrent kernel ----------------
// Consumer warps 0..15: ks4 = w&3, wm = (w>>2)&1, wb = (w>>3)&1.
// Producer warp 16 (tid 512). 8 chunks of K=256 per step into 2-stage ring:
// chunks 0..3: stage h0 (32KB), A from pinned SMEM; chunks 4..7: {h1 32KB, Wh1 16KB}.
// Per-stage fill j = 4t+n (n=ch>>1): full parity n&1, empty parity (n+1)&1
// (skip empty-wait only at t==0, ch<2).

__global__ void __launch_bounds__(NTHR, 1) lstm_persist(float* __restrict__ out)
{
    extern __shared__ char sm[];
    float* sB = (float*)(sm + SM_BI);
    float* P  = (float*)(sm + SM_RING);           // partial buffer (ring overlay)
    const uint32_t smBase = (uint32_t)__cvta_generic_to_shared(sm);
    const uint32_t fullB  = smBase + SM_MB;
    const uint32_t emptyB = smBase + SM_MB + 16;
    const uint32_t pinB   = smBase + SM_MB + 32;

    const int c    = blockIdx.x;
    const int tid  = threadIdx.x;
    const int w    = tid >> 5;
    const int lane = tid & 31;
    const int ks4  = w & 3;          // consumer K-quarter
    const int wm   = (w >> 2) & 1;   // prow half
    const int wb   = (w >> 3) & 1;   // batch half
    const int g4   = lane >> 2;
    const int t4   = lane & 3;
    const int v    = tid & 7;        // unit within CTA (consumers)
    const int b    = tid >> 3;       // batch (consumers, <64)
    const int u    = c * 8 + v;
    // h-image index for (u, b)
    const int ch_h = u >> 7;
    const int ks_h = (u >> 4) & 7;
    const int kk_h = u & 15;
    const int fidx = ((((ch_h * 8 + ks_h) * 8 + (b >> 3)) * 32
                       + ((b & 7) * 4 + ((kk_h & 7) >> 1))) * 4)
                     + ((kk_h >> 3) * 2) + (kk_h & 1);

    if (tid == 0) {
#pragma unroll
        for (int s = 0; s < NSTG; s++) {
            mbar_init(fullB  + s * 8, 1);
            mbar_init(emptyB + s * 8, 16);
        }
        mbar_init(pinB, 1);
    }
    if (tid < 32) sB[tid] = g_b1p[c * 32 + tid];
    asm volatile("fence.proxy.async.shared::cta;" ::: "memory");
    __syncthreads();

    // load pinned Wh0/Wx1 fragments (once)
    if (tid == 0) {
        mbar_expect_tx(pinB, 131072u);
        const uint4* w0 = g_A0f + (size_t)c * 4096;
        const uint4* w1 = g_A1f + (size_t)c * 4096;
#pragma unroll
        for (int i = 0; i < 4; i++) {
            bulk_g2s(smBase + SM_W0 + i * 16384, w0 + i * 1024, 16384, pinB);
            bulk_g2s(smBase + SM_W1 + i * 16384, w1 + i * 1024, 16384, pinB);
        }
    }

    float c0r = 0.f, c1r = 0.f;

    // preamble: h0[0] from G0[0] (h=0), zero h1[-1]
    if (tid < NCONS) {
        __half* h0w0 = g_h0I[0];
        __half* h1w0 = g_h1I[0];
        size_t gbase = (size_t)b * G_ + c * 32;
        float gi = g_G0[gbase + v];
        float go = g_G0[gbase + 16 + v];
        float gg = g_G0[gbase + 24 + v];
        float cn = sigf(gi) * tanhfast(gg);
        float hn = sigf(go) * tanhfast(cn);
        c0r = cn;
        h0w0[fidx] = __float2half(hn);
        h1w0[fidx] = __float2half(0.f);
    }
    mbar_wait(pinB, 0);
    gsync();

    const uint4* a2B = g_A2f + (size_t)c * (8 * 512);
    const uint4* W0p = (const uint4*)(sm + SM_W0);
    const uint4* W1p = (const uint4*)(sm + SM_W1);

    for (int t = 0; t < S_; t++) {
        const __half* bH0 = g_h0I[t & 1];          // h0[t]
        __half*       wH0 = g_h0I[(t + 1) & 1];
        const __half* bH1 = g_h1I[t & 1];          // h1[t-1]
        __half*       wH1 = g_h1I[(t + 1) & 1];

        // consumers: prefetch next layer0's G0 operands
        float p_gi = 0.f, p_gf = 0.f, p_go = 0.f, p_gg = 0.f;
        if (tid < NCONS && t + 1 < S_) {
            size_t gb = ((size_t)(t + 1) * B_ + b) * G_ + c * 32;
            p_gi = g_G0[gb + v];
            p_gf = g_G0[gb + 8 + v];
            p_go = g_G0[gb + 16 + v];
            p_gg = g_G0[gb + 24 + v];
        }

        float acc0[4][4], acc1[4][4];
#pragma unroll
        for (int bt = 0; bt < 4; bt++)
#pragma unroll
            for (int e = 0; e < 4; e++) { acc0[bt][e] = 0.f; acc1[bt][e] = 0.f; }

        if (tid == NCONS) {
            // ---------------- producer: 8 chunks of K=256 ----------------
            for (int ch = 0; ch < 8; ch++) {
                int s = ch & 1, n = ch >> 1;
                if (t > 0 || ch >= 2) {
                    mbar_wait(emptyB + s * 8, (uint32_t)((n + 1) & 1));
                }
                uint32_t sb = smBase + SM_RING + (uint32_t)s * STG_SZ;
                uint32_t fb = fullB + s * 8;
                if (ch < 4) {
                    mbar_expect_tx(fb, 32768u);
                    bulk_g2s(sb, bH0 + (size_t)ch * 16384, 32768, fb);
                } else {
                    int cc = ch - 4;
                    mbar_expect_tx(fb, 49152u);
                    bulk_g2s(sb,          bH1 + (size_t)cc * 16384, 32768, fb);
                    bulk_g2s(sb + 32768,  a2B + (size_t)cc * 1024,  16384, fb);
                }
            }
        } else if (tid < NCONS) {
            // ---------------- consumers ----------------
            // chunks 0..3 : pinned Wh0 -> acc0, pinned Wx1 -> acc1  (B = h0[t])
            for (int ch = 0; ch < 4; ch++) {
                int s = ch & 1, n = ch >> 1;
                mbar_wait(fullB + s * 8, (uint32_t)(n & 1));
                const uint2* Bf = (const uint2*)(sm + SM_RING + s * STG_SZ);
                const uint4* A0f = W0p + ch * 1024;
                const uint4* A1f = W1p + ch * 1024;
#pragma unroll
                for (int sc = 0; sc < 2; sc++) {
#pragma unroll
                    for (int j = 0; j < 2; j++) {
                        int ksub = ks4 * 2 + j;
                        int aidx = sc * 512 + (wm * 8 + ksub) * 32 + lane;
                        uint4 a0 = A0f[aidx];
                        uint4 a1 = A1f[aidx];
#pragma unroll
                        for (int bt = 0; bt < 4; bt++) {
                            uint2 bv = Bf[sc * 2048 + (ksub * 8 + wb * 4 + bt) * 32 + lane];
                            mma_f16(acc0[bt], a0, bv);
                            mma_f16(acc1[bt], a1, bv);
                        }
                    }
                }
                if (lane == 0) mbar_arrive(emptyB + s * 8);
            }
            // chunks 4..7 : staged Wh1 -> acc1  (B = h1[t-1])
            for (int ch = 4; ch < 8; ch++) {
                int s = ch & 1, n = ch >> 1;
                mbar_wait(fullB + s * 8, (uint32_t)(n & 1));
                const char* st = sm + SM_RING + s * STG_SZ;
                const uint2* Bf  = (const uint2*)st;
                const uint4* A0f = (const uint4*)(st + 32768);
#pragma unroll
                for (int sc = 0; sc < 2; sc++) {
#pragma unroll
                    for (int j = 0; j < 2; j++) {
                        int ksub = ks4 * 2 + j;
                        int aidx = sc * 512 + (wm * 8 + ksub) * 32 + lane;
                        uint4 a0 = A0f[aidx];
#pragma unroll
                        for (int bt = 0; bt < 4; bt++) {
                            uint2 bv = Bf[sc * 2048 + (ksub * 8 + wb * 4 + bt) * 32 + lane];
                            mma_f16(acc1[bt], a0, bv);
                        }
                    }
                }
                if (lane == 0) mbar_arrive(emptyB + s * 8);
            }
        }
        __syncthreads();   // all stages consumed; safe to overlay partials

        // ---- write K-split partials (4 splits x 4352 floats: [mat][row(32)x68]) ----
        if (tid < NCONS) {
            int r0 = wm * 16 + g4;
            int base0 = ks4 * 4352;
#pragma unroll
            for (int bt = 0; bt < 4; bt++) {
                int col = wb * 32 + bt * 8 + t4 * 2;
                *(float2*)&P[base0 + r0 * 68 + col]        = make_float2(acc0[bt][0], acc0[bt][1]);
                *(float2*)&P[base0 + (r0 + 8) * 68 + col]  = make_float2(acc0[bt][2], acc0[bt][3]);
                *(float2*)&P[base0 + 2176 + r0 * 68 + col]       = make_float2(acc1[bt][0], acc1[bt][1]);
                *(float2*)&P[base0 + 2176 + (r0 + 8) * 68 + col] = make_float2(acc1[bt][2], acc1[bt][3]);
            }
        }
        __syncthreads();

        // ---- reduce 4 partials + cell epilogues ----
        if (tid < NCONS) {
            float g0[4], g1[4];
#pragma unroll
            for (int q = 0; q < 4; q++) {
                int row = q * 8 + v;
                float s0 = 0.f, s1 = 0.f;
#pragma unroll
                for (int kr = 0; kr < 4; kr++) {
                    s0 += P[kr * 4352 + row * 68 + b];
                    s1 += P[kr * 4352 + 2176 + row * 68 + b];
                }
                g0[q] = s0; g1[q] = s1;
            }
            // layer 1 step t
            {
                float gi = g1[0] + sB[v];
                float gf = g1[1] + sB[8 + v];
                float go = g1[2] + sB[16 + v];
                float gg = g1[3] + sB[24 + v];
                float cn = sigf(gf) * c1r + sigf(gi) * tanhfast(gg);
                float hn = sigf(go) * tanhfast(cn);
                c1r = cn;
                out[((size_t)b * S_ + t) * H_ + u] = hn;
                wH1[fidx] = __float2half(hn);
                if (t == S_ - 1) {
                    out[(size_t)OUT_ELEMS + 1ull * BH_ + (size_t)b * H_ + u] = hn;
                    out[(size_t)OUT_ELEMS + 3ull * BH_ + (size_t)b * H_ + u] = cn;
                }
            }
            // layer 0 step t+1
            if (t < S_ - 1) {
                float gi = g0[0] + p_gi;
                float gf = g0[1] + p_gf;
                float go = g0[2] + p_go;
                float gg = g0[3] + p_gg;
                float cn = sigf(gf) * c0r + sigf(gi) * tanhfast(gg);
                float hn = sigf(go) * tanhfast(cn);
                c0r = cn;
                wH0[fidx] = __float2half(hn);
                if (t == S_ - 2) {
                    out[(size_t)OUT_ELEMS + (size_t)b * H_ + u]              = hn;
                    out[(size_t)OUT_ELEMS + 2ull * BH_ + (size_t)b * H_ + u] = cn;
                }
            }
        }
        if (t + 1 < S_) gsync();
    }
}

// ---------------- launch ----------------
extern "C" void kernel_launch(void* const* d_in, const int* in_sizes, int n_in,
                              void* d_out, int out_size)
{
    const float* x   = (const float*)d_in[0];
    const float* Wx0 = (const float*)d_in[1];
    const float* Wh0 = (const float*)d_in[2];
    const float* bx0 = (const float*)d_in[3];
    const float* bh0 = (const float*)d_in[4];
    const float* Wx1 = (const float*)d_in[5];
    const float* Wh1 = (const float*)d_in[6];
    const float* bx1 = (const float*)d_in[7];
    const float* bh1 = (const float*)d_in[8];
    float* out = (float*)d_out;

    static bool attr_done = false;
    if (!attr_done) {
        cudaFuncSetAttribute(lstm_persist,
                             cudaFuncAttributeMaxDynamicSharedMemorySize, SM_TOT);
        attr_done = true;
    }

    convert_nat<<<2048, 256>>>(Wx0, bx0, bh0, bx1, bh1);
    convert_frag<<<4096, 256>>>(Wh0, Wx1, Wh1);
    init_kernel<<<1, 32>>>();
    precompute_kernel<<<dim3(G_ / 128, (S_ * B_) / 128), 256>>>(x);
    lstm_persist<<<NCTA, NTHR, SM_TOT>>>(out);
}